// round 1
// baseline (speedup 1.0000x reference)
#include <cuda_runtime.h>
#include <math.h>

#define HD 2048      // hidden size
#define ID 1408      // moe intermediate
#define NE 16        // routed experts
#define TK 4         // top-k
#define NT 1024      // tokens
#define SID 2816     // shared intermediate
#define RSCALE 2.5f

// ---------------- scratch (device globals: no allocation allowed) ----------
__device__ int   d_cnt[NE];
__device__ int   d_tok[NE * NT];
__device__ float d_wt [NE * NT];
__device__ float d_hbuf[NE * NT * ID];   // 92.3 MB: per-expert slot-major h
__device__ float d_hsh [NT * SID];       // 11.5 MB: shared-expert h

// ---------------- init ----------------
__global__ void init_kernel() {
    if (threadIdx.x < NE) d_cnt[threadIdx.x] = 0;
}

// ---------------- gate: sigmoid + group top-2 + top-4 + normalize ----------
__global__ void gate_kernel(const float* __restrict__ x,
                            const float* __restrict__ gw,
                            const float* __restrict__ gb) {
    const int t = blockIdx.x;
    __shared__ float s_sc[NE];
    const int wid = threadIdx.x >> 5;
    const int lane = threadIdx.x & 31;
    const float* xr = x + (size_t)t * HD;
    const float* wr = gw + (size_t)wid * HD;
    float acc = 0.f;
    for (int k = lane; k < HD; k += 32) acc += xr[k] * wr[k];
    #pragma unroll
    for (int o = 16; o; o >>= 1) acc += __shfl_xor_sync(0xffffffffu, acc, o);
    if (lane == 0) s_sc[wid] = 1.f / (1.f + expf(-acc)) + gb[wid];
    __syncthreads();
    if (threadIdx.x != 0) return;

    float sc[NE];
    #pragma unroll
    for (int e = 0; e < NE; e++) sc[e] = s_sc[e];

    // group scores = max over each group of 4
    float gs[4];
    #pragma unroll
    for (int g = 0; g < 4; g++) {
        float m = sc[g * 4];
        #pragma unroll
        for (int j = 1; j < 4; j++) m = fmaxf(m, sc[g * 4 + j]);
        gs[g] = m;
    }
    // top-2 groups, lowest-index tie-break (strict >)
    int g0 = 0;
    for (int g = 1; g < 4; g++) if (gs[g] > gs[g0]) g0 = g;
    int g1 = -1;
    for (int g = 0; g < 4; g++) {
        if (g == g0) continue;
        if (g1 < 0 || gs[g] > gs[g1]) g1 = g;
    }
    float masked[NE];
    #pragma unroll
    for (int e = 0; e < NE; e++) {
        int g = e >> 2;
        masked[e] = (g == g0 || g == g1) ? sc[e] : 0.f;
    }
    // top-4 of masked, lowest-index tie-break
    int   idx[TK];
    float w[TK];
    bool  used[NE];
    #pragma unroll
    for (int e = 0; e < NE; e++) used[e] = false;
    float wsum = 0.f;
    for (int k = 0; k < TK; k++) {
        int best = -1;
        for (int e = 0; e < NE; e++) {
            if (used[e]) continue;
            if (best < 0 || masked[e] > masked[best]) best = e;
        }
        used[best] = true;
        idx[k] = best;
        w[k] = masked[best];
        wsum += masked[best];
    }
    const float inv = 1.f / (wsum + 1e-6f);
    for (int k = 0; k < TK; k++) {
        int e = idx[k];
        int pos = atomicAdd(&d_cnt[e], 1);
        d_tok[e * NT + pos] = t;
        d_wt [e * NT + pos] = w[k] * inv * RSCALE;
    }
}

// ---------------- dual GEMM (gate & up) + SiLU fused ----------------------
// C[m,n] over A[M,K] (gathered token rows) x Wg/Wu[N,K] (K-major) -> h[m,n]
template <bool GATHER>
__global__ void dual_gemm_silu(const float* __restrict__ X,
                               const float* __restrict__ Wg_all,
                               const float* __restrict__ Wu_all,
                               float* __restrict__ Hall,
                               int N, int K) {
    const int e = blockIdx.z;
    int M;
    const int* toks = nullptr;
    const float *Wg, *Wu;
    float* Ho;
    if (GATHER) {
        M = d_cnt[e];
        toks = d_tok + e * NT;
        Wg = Wg_all + (size_t)e * ID * HD;
        Wu = Wu_all + (size_t)e * ID * HD;
        Ho = Hall + (size_t)e * NT * ID;
    } else {
        M = NT;
        Wg = Wg_all; Wu = Wu_all; Ho = Hall;
    }
    if ((int)(blockIdx.y * 64) >= M) return;

    __shared__ float As[16][64];
    __shared__ float Bg[16][64];
    __shared__ float Bu[16][64];

    const int tid = threadIdx.x;
    const int lr = tid >> 2;            // 0..63
    const int lc = (tid & 3) << 2;      // 0,4,8,12
    const int m_load = blockIdx.y * 64 + lr;
    const int n_load = blockIdx.x * 64 + lr;
    const bool a_valid = m_load < M;
    int a_row = 0;
    if (a_valid) a_row = GATHER ? toks[m_load] : m_load;
    const float4* Arow = (const float4*)(X  + (size_t)a_row  * K);
    const float4* Grow = (const float4*)(Wg + (size_t)n_load * K);
    const float4* Urow = (const float4*)(Wu + (size_t)n_load * K);

    const int ty = tid >> 4, tx = tid & 15;
    float accg[4][4] = {}, accu[4][4] = {};

    for (int k0 = 0; k0 < K; k0 += 16) {
        const int kv = (k0 + lc) >> 2;
        float4 av = a_valid ? Arow[kv] : make_float4(0.f, 0.f, 0.f, 0.f);
        float4 gv = Grow[kv];
        float4 uv = Urow[kv];
        __syncthreads();
        As[lc + 0][lr] = av.x; As[lc + 1][lr] = av.y; As[lc + 2][lr] = av.z; As[lc + 3][lr] = av.w;
        Bg[lc + 0][lr] = gv.x; Bg[lc + 1][lr] = gv.y; Bg[lc + 2][lr] = gv.z; Bg[lc + 3][lr] = gv.w;
        Bu[lc + 0][lr] = uv.x; Bu[lc + 1][lr] = uv.y; Bu[lc + 2][lr] = uv.z; Bu[lc + 3][lr] = uv.w;
        __syncthreads();
        #pragma unroll
        for (int kk = 0; kk < 16; kk++) {
            float4 a = *(const float4*)&As[kk][ty * 4];
            float4 g = *(const float4*)&Bg[kk][tx * 4];
            float4 u = *(const float4*)&Bu[kk][tx * 4];
            float ar[4] = {a.x, a.y, a.z, a.w};
            float gr[4] = {g.x, g.y, g.z, g.w};
            float ur[4] = {u.x, u.y, u.z, u.w};
            #pragma unroll
            for (int i = 0; i < 4; i++)
                #pragma unroll
                for (int j = 0; j < 4; j++) {
                    accg[i][j] = fmaf(ar[i], gr[j], accg[i][j]);
                    accu[i][j] = fmaf(ar[i], ur[j], accu[i][j]);
                }
        }
    }
    #pragma unroll
    for (int i = 0; i < 4; i++) {
        int m = blockIdx.y * 64 + ty * 4 + i;
        if (m >= M) continue;
        float* orow = Ho + (size_t)m * N + blockIdx.x * 64 + tx * 4;
        #pragma unroll
        for (int j = 0; j < 4; j++) {
            float gval = accg[i][j];
            float s = gval / (1.f + __expf(-gval));
            orow[j] = s * accu[i][j];
        }
    }
}

// ---------------- down GEMM: h[M,K] x Wd[N,K] -> out ----------------------
template <bool ROUTED>
__global__ void down_gemm(const float* __restrict__ Hall,
                          const float* __restrict__ Wd_all,
                          float* __restrict__ Out,
                          int N, int K) {
    const int e = blockIdx.z;
    int M;
    const float *Hin, *Wd;
    if (ROUTED) {
        M = d_cnt[e];
        Hin = Hall + (size_t)e * NT * ID;
        Wd = Wd_all + (size_t)e * HD * ID;
    } else {
        M = NT; Hin = Hall; Wd = Wd_all;
    }
    if ((int)(blockIdx.y * 64) >= M) return;

    __shared__ float As[16][64];
    __shared__ float Bs[16][64];

    const int tid = threadIdx.x;
    const int lr = tid >> 2;
    const int lc = (tid & 3) << 2;
    const int m_load = blockIdx.y * 64 + lr;
    const int n_load = blockIdx.x * 64 + lr;
    const bool a_valid = m_load < M;
    const float4* Arow = (const float4*)(Hin + (size_t)(a_valid ? m_load : 0) * K);
    const float4* Brow = (const float4*)(Wd  + (size_t)n_load * K);

    const int ty = tid >> 4, tx = tid & 15;
    float acc[4][4] = {};

    for (int k0 = 0; k0 < K; k0 += 16) {
        const int kv = (k0 + lc) >> 2;
        float4 av = a_valid ? Arow[kv] : make_float4(0.f, 0.f, 0.f, 0.f);
        float4 bv = Brow[kv];
        __syncthreads();
        As[lc + 0][lr] = av.x; As[lc + 1][lr] = av.y; As[lc + 2][lr] = av.z; As[lc + 3][lr] = av.w;
        Bs[lc + 0][lr] = bv.x; Bs[lc + 1][lr] = bv.y; Bs[lc + 2][lr] = bv.z; Bs[lc + 3][lr] = bv.w;
        __syncthreads();
        #pragma unroll
        for (int kk = 0; kk < 16; kk++) {
            float4 a = *(const float4*)&As[kk][ty * 4];
            float4 b = *(const float4*)&Bs[kk][tx * 4];
            float ar[4] = {a.x, a.y, a.z, a.w};
            float br[4] = {b.x, b.y, b.z, b.w};
            #pragma unroll
            for (int i = 0; i < 4; i++)
                #pragma unroll
                for (int j = 0; j < 4; j++)
                    acc[i][j] = fmaf(ar[i], br[j], acc[i][j]);
        }
    }
    #pragma unroll
    for (int i = 0; i < 4; i++) {
        int m = blockIdx.y * 64 + ty * 4 + i;
        if (m >= M) continue;
        if (ROUTED) {
            int token = d_tok[e * NT + m];
            float wt  = d_wt [e * NT + m];
            float* orow = Out + (size_t)token * N + blockIdx.x * 64 + tx * 4;
            #pragma unroll
            for (int j = 0; j < 4; j++) atomicAdd(&orow[j], wt * acc[i][j]);
        } else {
            float* orow = Out + (size_t)m * N + blockIdx.x * 64 + tx * 4;
            #pragma unroll
            for (int j = 0; j < 4; j++) orow[j] = acc[i][j];
        }
    }
}

// ---------------- launch ----------------
extern "C" void kernel_launch(void* const* d_in, const int* in_sizes, int n_in,
                              void* d_out, int out_size) {
    const float* x       = (const float*)d_in[0];
    const float* gate_w  = (const float*)d_in[1];
    const float* gate_b  = (const float*)d_in[2];
    const float* w_gate  = (const float*)d_in[3];
    const float* w_up    = (const float*)d_in[4];
    const float* w_down  = (const float*)d_in[5];
    const float* sw_gate = (const float*)d_in[6];
    const float* sw_up   = (const float*)d_in[7];
    const float* sw_down = (const float*)d_in[8];
    float* out = (float*)d_out;

    float* hbuf; cudaGetSymbolAddress((void**)&hbuf, d_hbuf);
    float* hsh;  cudaGetSymbolAddress((void**)&hsh,  d_hsh);

    init_kernel<<<1, 32>>>();
    gate_kernel<<<NT, 512>>>(x, gate_w, gate_b);

    // routed gate/up + silu  (per-expert gathered tokens)
    dual_gemm_silu<true><<<dim3(ID / 64, NT / 64, NE), 256>>>(
        x, w_gate, w_up, hbuf, ID, HD);
    // shared gate/up + silu (dense)
    dual_gemm_silu<false><<<dim3(SID / 64, NT / 64, 1), 256>>>(
        x, sw_gate, sw_up, hsh, SID, HD);
    // shared down: plain writes initialize d_out fully
    down_gemm<false><<<dim3(HD / 64, NT / 64, 1), 256>>>(
        hsh, sw_down, out, HD, SID);
    // routed down: atomic scatter-add on top of shared result
    down_gemm<true><<<dim3(HD / 64, NT / 64, NE), 256>>>(
        hbuf, w_down, out, HD, ID);
}

// round 3
// speedup vs baseline: 3.3928x; 3.3928x over previous
#include <cuda_runtime.h>
#include <math.h>
#include <cstdint>

#define HD 2048
#define ID 1408
#define NE 16
#define TK 4
#define NT 1024
#define SID 2816
#define RSCALE 2.5f

// ---------------- scratch ----------------
__device__ int   d_cnt[NE];
__device__ int   d_tok[NE * NT];
__device__ float d_wt [NE * NT];
__device__ float d_hbuf[NE * NT * ID];   // per-expert slot-major h
__device__ float d_hsh [NT * SID];       // shared-expert h

// ---------------- PTX helpers ----------------
__device__ __forceinline__ uint32_t smem_u32(const void* p) {
    uint32_t a;
    asm("{ .reg .u64 t; cvta.to.shared.u64 t, %1; cvt.u32.u64 %0, t; }"
        : "=r"(a) : "l"(p));
    return a;
}
#define CP_ASYNC(dst, src, sz) \
    asm volatile("cp.async.cg.shared.global [%0], [%1], 16, %2;" \
                 :: "r"(dst), "l"(src), "r"(sz) : "memory")
#define CP_COMMIT() asm volatile("cp.async.commit_group;" ::: "memory")
#define CP_WAIT(n)  asm volatile("cp.async.wait_group %0;" :: "n"(n) : "memory")

__device__ __forceinline__ uint32_t f2tf(float f) {
    uint32_t r;
    asm("cvt.rna.tf32.f32 %0, %1;" : "=r"(r) : "f"(f));
    return r;
}
// m16n8k8 tf32 mma, fp32 accumulate
__device__ __forceinline__ void mma8(float* c, const uint32_t* a, const uint32_t* b) {
    asm volatile(
        "mma.sync.aligned.m16n8k8.row.col.f32.tf32.tf32.f32 "
        "{%0,%1,%2,%3}, {%4,%5,%6,%7}, {%8,%9}, {%0,%1,%2,%3};"
        : "+f"(c[0]), "+f"(c[1]), "+f"(c[2]), "+f"(c[3])
        : "r"(a[0]), "r"(a[1]), "r"(a[2]), "r"(a[3]), "r"(b[0]), "r"(b[1]));
}
__device__ __forceinline__ float silu(float g) { return g / (1.f + __expf(-g)); }

#define AROW 20   // padded row stride in floats (conflict-free, 16B-aligned)

// ---------------- init ----------------
__global__ void init_kernel() {
    if (threadIdx.x < NE) d_cnt[threadIdx.x] = 0;
}

// ---------------- gate ----------------
__global__ void gate_kernel(const float* __restrict__ x,
                            const float* __restrict__ gw,
                            const float* __restrict__ gb) {
    const int t = blockIdx.x;
    __shared__ float s_sc[NE];
    const int wid = threadIdx.x >> 5;
    const int lane = threadIdx.x & 31;
    const float* xr = x + (size_t)t * HD;
    const float* wr = gw + (size_t)wid * HD;
    float acc = 0.f;
    for (int k = lane; k < HD; k += 32) acc += xr[k] * wr[k];
    #pragma unroll
    for (int o = 16; o; o >>= 1) acc += __shfl_xor_sync(0xffffffffu, acc, o);
    if (lane == 0) s_sc[wid] = 1.f / (1.f + expf(-acc)) + gb[wid];
    __syncthreads();
    if (threadIdx.x != 0) return;

    float sc[NE];
    #pragma unroll
    for (int e = 0; e < NE; e++) sc[e] = s_sc[e];
    float gs[4];
    #pragma unroll
    for (int g = 0; g < 4; g++) {
        float m = sc[g * 4];
        #pragma unroll
        for (int j = 1; j < 4; j++) m = fmaxf(m, sc[g * 4 + j]);
        gs[g] = m;
    }
    int g0 = 0;
    for (int g = 1; g < 4; g++) if (gs[g] > gs[g0]) g0 = g;
    int g1 = -1;
    for (int g = 0; g < 4; g++) {
        if (g == g0) continue;
        if (g1 < 0 || gs[g] > gs[g1]) g1 = g;
    }
    float masked[NE];
    #pragma unroll
    for (int e = 0; e < NE; e++) {
        int g = e >> 2;
        masked[e] = (g == g0 || g == g1) ? sc[e] : 0.f;
    }
    int idx[TK]; float w[TK]; bool used[NE];
    #pragma unroll
    for (int e = 0; e < NE; e++) used[e] = false;
    float wsum = 0.f;
    for (int k = 0; k < TK; k++) {
        int best = -1;
        for (int e = 0; e < NE; e++) {
            if (used[e]) continue;
            if (best < 0 || masked[e] > masked[best]) best = e;
        }
        used[best] = true;
        idx[k] = best; w[k] = masked[best]; wsum += masked[best];
    }
    const float inv = 1.f / (wsum + 1e-6f);
    for (int k = 0; k < TK; k++) {
        int e = idx[k];
        int pos = atomicAdd(&d_cnt[e], 1);
        d_tok[e * NT + pos] = t;
        d_wt [e * NT + pos] = w[k] * inv * RSCALE;
    }
}

// ---------------- GEMM1: dual (gate,up) mma.sync tf32 + SiLU ----------------
// Tile 128(M) x 64(N), 256 threads (8 warps, 2x4), warp = 64x16 dual.
// Smem stage: A[128][20] + Bg[64][20] + Bu[64][20] = 20480 B; 3 stages.
#define G1_STAGE 20480
#define G1_SMEM  (512 + 3 * G1_STAGE)
template <bool GATHER>
__global__ void __launch_bounds__(256, 1)
gemm1_mma(const float* __restrict__ X,
          const float* __restrict__ Wg_, const float* __restrict__ Wu_,
          float* __restrict__ H_, int ldH, int K) {
    const int e = blockIdx.z;
    int M; const int* toks = nullptr; const float *Wg, *Wu; float* Ho;
    if (GATHER) {
        M = d_cnt[e]; toks = d_tok + e * NT;
        Wg = Wg_ + (size_t)e * ID * HD;
        Wu = Wu_ + (size_t)e * ID * HD;
        Ho = H_ + (size_t)e * NT * ID;
    } else {
        M = NT; Wg = Wg_; Wu = Wu_; Ho = H_;
    }
    const int m0 = blockIdx.y * 128;
    if (m0 >= M) return;
    const int n0 = blockIdx.x * 64;

    extern __shared__ char smem[];
    int* s_tok = (int*)smem;
    const int tid = threadIdx.x, lane = tid & 31, wid = tid >> 5;
    const int wr = wid >> 2, wc = wid & 3;
    if (GATHER && tid < 128) s_tok[tid] = (m0 + tid < M) ? toks[m0 + tid] : 0;
    __syncthreads();

    // loader: row = tid/4 (0..63), ch = tid%4; A covers rows lrow & lrow+64
    const int lrow = tid >> 2, lch = tid & 3;
    const bool ok0 = (m0 + lrow) < M;
    const bool ok1 = (m0 + lrow + 64) < M;
    int ar0 = 0, ar1 = 0;
    if (GATHER) { ar0 = ok0 ? s_tok[lrow] : 0; ar1 = ok1 ? s_tok[lrow + 64] : 0; }
    else        { ar0 = ok0 ? m0 + lrow : 0;   ar1 = ok1 ? m0 + lrow + 64 : 0; }
    const float* A0 = X + (size_t)ar0 * K + lch * 4;
    const float* A1 = X + (size_t)ar1 * K + lch * 4;
    const float* G0 = Wg + (size_t)(n0 + lrow) * K + lch * 4;
    const float* U0 = Wu + (size_t)(n0 + lrow) * K + lch * 4;
    const uint32_t sb = smem_u32(smem) + 512;
    const uint32_t w0 = (uint32_t)((lrow * AROW + lch * 4) * 4);
    const uint32_t sz0 = ok0 ? 16u : 0u, sz1 = ok1 ? 16u : 0u;

    const int C = K >> 4;
    auto load = [&](int c, int buf) {
        const int off = c * 16;
        const uint32_t d = sb + buf * G1_STAGE + w0;
        CP_ASYNC(d,                          A0 + off, sz0);
        CP_ASYNC(d + 64 * AROW * 4,          A1 + off, sz1);
        CP_ASYNC(d + 10240,                  G0 + off, 16);
        CP_ASYNC(d + 15360,                  U0 + off, 16);
    };

    float cg[4][2][4] = {}, cu[4][2][4] = {};
    #pragma unroll
    for (int s = 0; s < 2; s++) { if (s < C) load(s, s); CP_COMMIT(); }

    const float* SBASE = (const float*)(smem + 512);
    const int l4 = lane >> 2, lm = lane & 3;
    #pragma unroll 1
    for (int c = 0; c < C; c++) {
        CP_WAIT(1);
        __syncthreads();
        const int nc = c + 2;
        if (nc < C) load(nc, nc % 3);
        CP_COMMIT();
        const float* SA = SBASE + (c % 3) * (G1_STAGE / 4);
        const float* SG = SA + 2560;
        const float* SU = SA + 3840;
        #pragma unroll
        for (int ks = 0; ks < 2; ks++) {
            const int k0 = ks * 8 + lm;
            uint32_t a[4][4];
            #pragma unroll
            for (int mi = 0; mi < 4; mi++) {
                const float* p = SA + (wr * 64 + mi * 16 + l4) * AROW + k0;
                a[mi][0] = f2tf(p[0]);
                a[mi][1] = f2tf(p[8 * AROW]);
                a[mi][2] = f2tf(p[4]);
                a[mi][3] = f2tf(p[8 * AROW + 4]);
            }
            #pragma unroll
            for (int ni = 0; ni < 2; ni++) {
                const float* pg = SG + (wc * 16 + ni * 8 + l4) * AROW + k0;
                const float* pu = SU + (wc * 16 + ni * 8 + l4) * AROW + k0;
                uint32_t bg[2] = { f2tf(pg[0]), f2tf(pg[4]) };
                uint32_t bu[2] = { f2tf(pu[0]), f2tf(pu[4]) };
                #pragma unroll
                for (int mi = 0; mi < 4; mi++) {
                    mma8(cg[mi][ni], a[mi], bg);
                    mma8(cu[mi][ni], a[mi], bu);
                }
            }
        }
    }
    // epilogue: silu(g)*u from fragments, direct to global
    #pragma unroll
    for (int mi = 0; mi < 4; mi++)
        #pragma unroll
        for (int ni = 0; ni < 2; ni++) {
            const int r = m0 + wr * 64 + mi * 16 + l4;
            const int cc = n0 + wc * 16 + ni * 8 + 2 * lm;
            if (r < M) {
                float2 v = { silu(cg[mi][ni][0]) * cu[mi][ni][0],
                             silu(cg[mi][ni][1]) * cu[mi][ni][1] };
                *(float2*)(Ho + (size_t)r * ldH + cc) = v;
            }
            if (r + 8 < M) {
                float2 v = { silu(cg[mi][ni][2]) * cu[mi][ni][2],
                             silu(cg[mi][ni][3]) * cu[mi][ni][3] };
                *(float2*)(Ho + (size_t)(r + 8) * ldH + cc) = v;
            }
        }
}

// ---------------- GEMM2: down mma.sync tf32 ----------------
// Tile 128(M) x 128(N), 256 threads (8 warps, 2x4), warp = 64x32.
// Smem stage: A[128][20] + B[128][20] = 20480 B; 4 stages.
#define G2_STAGE 20480
#define G2_SMEM  (1024 + 4 * G2_STAGE)
template <bool ROUTED>
__global__ void __launch_bounds__(256, 2)
gemm2_mma(const float* __restrict__ Hin_, const float* __restrict__ Wd_,
          float* __restrict__ Out, int K) {
    const int e = blockIdx.z;
    int M; const float *Hin, *Wd; const int* toks = nullptr; const float* wts = nullptr;
    if (ROUTED) {
        M = d_cnt[e];
        Hin = Hin_ + (size_t)e * NT * ID;
        Wd  = Wd_  + (size_t)e * HD * ID;
        toks = d_tok + e * NT; wts = d_wt + e * NT;
    } else {
        M = NT; Hin = Hin_; Wd = Wd_;
    }
    const int m0 = blockIdx.y * 128;
    if (m0 >= M) return;
    const int n0 = blockIdx.x * 128;

    extern __shared__ char smem[];
    int*   s_tok = (int*)smem;
    float* s_wt  = (float*)(smem + 512);
    const int tid = threadIdx.x, lane = tid & 31, wid = tid >> 5;
    const int wr = wid >> 2, wc = wid & 3;
    if (ROUTED && tid < 128) {
        const bool ok = m0 + tid < M;
        s_tok[tid] = ok ? toks[m0 + tid] : 0;
        s_wt [tid] = ok ? wts [m0 + tid] : 0.f;
    }
    __syncthreads();

    const int lrow = tid >> 2, lch = tid & 3;
    const bool ok0 = (m0 + lrow) < M;
    const bool ok1 = (m0 + lrow + 64) < M;
    const float* A0 = Hin + (size_t)(ok0 ? m0 + lrow : 0) * K + lch * 4;
    const float* A1 = Hin + (size_t)(ok1 ? m0 + lrow + 64 : 0) * K + lch * 4;
    const float* B0 = Wd + (size_t)(n0 + lrow) * K + lch * 4;
    const float* B1 = Wd + (size_t)(n0 + lrow + 64) * K + lch * 4;
    const uint32_t sb = smem_u32(smem) + 1024;
    const uint32_t w0 = (uint32_t)((lrow * AROW + lch * 4) * 4);
    const uint32_t sz0 = ok0 ? 16u : 0u, sz1 = ok1 ? 16u : 0u;

    const int C = K >> 4;
    auto load = [&](int c, int buf) {
        const int off = c * 16;
        const uint32_t d = sb + buf * G2_STAGE + w0;
        CP_ASYNC(d,                  A0 + off, sz0);
        CP_ASYNC(d + 64 * AROW * 4,  A1 + off, sz1);
        CP_ASYNC(d + 10240,                 B0 + off, 16);
        CP_ASYNC(d + 10240 + 64 * AROW * 4, B1 + off, 16);
    };

    float acc[4][4][4] = {};
    #pragma unroll
    for (int s = 0; s < 3; s++) { if (s < C) load(s, s); CP_COMMIT(); }

    const float* SBASE = (const float*)(smem + 1024);
    const int l4 = lane >> 2, lm = lane & 3;
    #pragma unroll 1
    for (int c = 0; c < C; c++) {
        CP_WAIT(2);
        __syncthreads();
        const int nc = c + 3;
        if (nc < C) load(nc, nc & 3);
        CP_COMMIT();
        const float* SA = SBASE + (c & 3) * (G2_STAGE / 4);
        const float* SB = SA + 2560;
        #pragma unroll
        for (int ks = 0; ks < 2; ks++) {
            const int k0 = ks * 8 + lm;
            uint32_t a[4][4];
            #pragma unroll
            for (int mi = 0; mi < 4; mi++) {
                const float* p = SA + (wr * 64 + mi * 16 + l4) * AROW + k0;
                a[mi][0] = f2tf(p[0]);
                a[mi][1] = f2tf(p[8 * AROW]);
                a[mi][2] = f2tf(p[4]);
                a[mi][3] = f2tf(p[8 * AROW + 4]);
            }
            #pragma unroll
            for (int ni = 0; ni < 4; ni++) {
                const float* pb = SB + (wc * 32 + ni * 8 + l4) * AROW + k0;
                uint32_t b[2] = { f2tf(pb[0]), f2tf(pb[4]) };
                #pragma unroll
                for (int mi = 0; mi < 4; mi++)
                    mma8(acc[mi][ni], a[mi], b);
            }
        }
    }
    // epilogue
    #pragma unroll
    for (int mi = 0; mi < 4; mi++) {
        const int rl0 = wr * 64 + mi * 16 + l4;
        #pragma unroll
        for (int ni = 0; ni < 4; ni++) {
            const int cc = n0 + wc * 32 + ni * 8 + 2 * lm;
            #pragma unroll
            for (int h = 0; h < 2; h++) {
                const int rl = rl0 + h * 8;
                if (m0 + rl >= M) continue;
                const float v0 = acc[mi][ni][2 * h + 0];
                const float v1 = acc[mi][ni][2 * h + 1];
                if (ROUTED) {
                    const float w = s_wt[rl];
                    float* o = Out + (size_t)s_tok[rl] * HD + cc;
                    atomicAdd(o + 0, w * v0);
                    atomicAdd(o + 1, w * v1);
                } else {
                    float2 v = { v0, v1 };
                    *(float2*)(Out + (size_t)(m0 + rl) * HD + cc) = v;
                }
            }
        }
    }
}

// ---------------- launch ----------------
extern "C" void kernel_launch(void* const* d_in, const int* in_sizes, int n_in,
                              void* d_out, int out_size) {
    const float* x       = (const float*)d_in[0];
    const float* gate_w  = (const float*)d_in[1];
    const float* gate_b  = (const float*)d_in[2];
    const float* w_gate  = (const float*)d_in[3];
    const float* w_up    = (const float*)d_in[4];
    const float* w_down  = (const float*)d_in[5];
    const float* sw_gate = (const float*)d_in[6];
    const float* sw_up   = (const float*)d_in[7];
    const float* sw_down = (const float*)d_in[8];
    float* out = (float*)d_out;

    float* hbuf; cudaGetSymbolAddress((void**)&hbuf, d_hbuf);
    float* hsh;  cudaGetSymbolAddress((void**)&hsh,  d_hsh);

    cudaFuncSetAttribute(gemm1_mma<true>,  cudaFuncAttributeMaxDynamicSharedMemorySize, G1_SMEM);
    cudaFuncSetAttribute(gemm1_mma<false>, cudaFuncAttributeMaxDynamicSharedMemorySize, G1_SMEM);
    cudaFuncSetAttribute(gemm2_mma<true>,  cudaFuncAttributeMaxDynamicSharedMemorySize, G2_SMEM);
    cudaFuncSetAttribute(gemm2_mma<false>, cudaFuncAttributeMaxDynamicSharedMemorySize, G2_SMEM);

    init_kernel<<<1, 32>>>();
    gate_kernel<<<NT, 512>>>(x, gate_w, gate_b);

    // routed gate/up + silu
    gemm1_mma<true><<<dim3(ID / 64, NT / 128, NE), 256, G1_SMEM>>>(
        x, w_gate, w_up, hbuf, ID, HD);
    // shared gate/up + silu
    gemm1_mma<false><<<dim3(SID / 64, NT / 128, 1), 256, G1_SMEM>>>(
        x, sw_gate, sw_up, hsh, SID, HD);
    // shared down: plain writes initialize d_out fully
    gemm2_mma<false><<<dim3(HD / 128, NT / 128, 1), 256, G2_SMEM>>>(
        hsh, sw_down, out, SID);
    // routed down: atomic scatter-add on top of shared result
    gemm2_mma<true><<<dim3(HD / 128, NT / 128, NE), 256, G2_SMEM>>>(
        hbuf, w_down, out, ID);
}